// round 1
// baseline (speedup 1.0000x reference)
#include <cuda_runtime.h>
#include <cuda_bf16.h>
#include <math.h>

#define BATCH 16384
#define OBS   512
#define ACT   256
#define NE    16
#define TOPK  4
#define ROWS_PER_CHUNK 64
#define MAX_CHUNKS (BATCH / ROWS_PER_CHUNK)   // 256 worst case per expert

// ---------------- static device scratch (no runtime allocation) ----------------
__device__ int   g_cnt[NE];
__device__ int   g_ridx[NE * BATCH];   // packed b*4 + slot
__device__ float g_w[NE * BATCH];
// slot-separated contributions: [mat(2)][slot(4)][BATCH][ACT]  -> 134 MB
__device__ float g_scr[(size_t)2 * 4 * BATCH * ACT];

// ---------------- kernel 1: router (logits -> softmax -> top4 -> lists) ----------------
__global__ void router_kernel(const float* __restrict__ x,
                              const float* __restrict__ rw,
                              const float* __restrict__ rb) {
    int warp = threadIdx.x >> 5;
    int lane = threadIdx.x & 31;
    int b = blockIdx.x * 4 + warp;
    if (b >= BATCH) return;

    // load this row of x (512 floats, strided by lane)
    float xr[16];
#pragma unroll
    for (int k = 0; k < 16; k++) xr[k] = x[(size_t)b * OBS + k * 32 + lane];

    float logit = 0.f;
    for (int e = 0; e < NE; e++) {
        const float* w = rw + e * OBS;
        float acc = 0.f;
#pragma unroll
        for (int k = 0; k < 16; k++) acc = fmaf(xr[k], w[k * 32 + lane], acc);
#pragma unroll
        for (int off = 16; off; off >>= 1) acc += __shfl_xor_sync(0xffffffffu, acc, off);
        if (lane == e) logit = acc + rb[e];
    }

    // softmax over lanes 0..15
    float v = (lane < NE) ? logit : -1e30f;
    float m = v;
#pragma unroll
    for (int off = 16; off; off >>= 1) m = fmaxf(m, __shfl_xor_sync(0xffffffffu, m, off));
    float p = (lane < NE) ? expf(v - m) : 0.f;
    float s = p;
#pragma unroll
    for (int off = 16; off; off >>= 1) s += __shfl_xor_sync(0xffffffffu, s, off);
    float prob = p / s;

    // top-4, lowest-index tie-break (matches jax top_k)
    float cur = (lane < NE) ? prob : -1.f;
#pragma unroll
    for (int slot = 0; slot < TOPK; slot++) {
        float mx = cur;
#pragma unroll
        for (int off = 16; off; off >>= 1) mx = fmaxf(mx, __shfl_xor_sync(0xffffffffu, mx, off));
        unsigned bal = __ballot_sync(0xffffffffu, cur == mx);
        int sel = __ffs(bal) - 1;
        if (lane == sel) {
            int pos = atomicAdd(&g_cnt[lane], 1);
            g_ridx[lane * BATCH + pos] = b * 4 + slot;
            g_w[lane * BATCH + pos]    = prob;
            cur = -1.f;
        }
    }
}

// ---------------- kernel 2: grouped expert GEMM (gather rows, fp32 register tile) ----------------
__global__ void __launch_bounds__(256) expert_kernel(const float* __restrict__ x,
                                                     const float* __restrict__ mw,
                                                     const float* __restrict__ mb,
                                                     const float* __restrict__ lw,
                                                     const float* __restrict__ lb) {
    const int e = blockIdx.y;
    const int n = g_cnt[e];
    const int start = blockIdx.x * ROWS_PER_CHUNK;
    if (start >= n) return;
    const int mrows = min(ROWS_PER_CHUNK, n - start);

    __shared__ float4 xs4[ROWS_PER_CHUNK * 32];   // 64 rows x 128 floats (K-chunk) = 32 KB
    __shared__ int   bs[ROWS_PER_CHUNK];
    __shared__ int   ss[ROWS_PER_CHUNK];
    __shared__ float ws[ROWS_PER_CHUNK];

    const int t = threadIdx.x;
    if (t < ROWS_PER_CHUNK) {
        if (t < mrows) {
            int entry = g_ridx[e * BATCH + start + t];
            bs[t] = entry >> 2;
            ss[t] = entry & 3;
            ws[t] = g_w[e * BATCH + start + t];
        } else {
            bs[t] = 0; ss[t] = 0; ws[t] = 0.f;
        }
    }

    const int ag = t & 31;     // act group: acts a = ag + i*32, i<8
    const int rg = t >> 5;     // row group: rows r = rg*8 + j, j<8
    const float4* x4 = (const float4*)x;

    for (int mat = 0; mat < 2; ++mat) {
        const float4* W4   = (const float4*)(mat ? lw : mw) + (size_t)e * ACT * (OBS / 4);
        const float*  bias = (mat ? lb : mb) + e * ACT;

        float acc[8][8];
#pragma unroll
        for (int j = 0; j < 8; j++)
#pragma unroll
            for (int i = 0; i < 8; i++) acc[j][i] = 0.f;

        for (int kc = 0; kc < 4; kc++) {
            const int kq = kc * 32;                 // K-chunk offset in float4 units
            __syncthreads();                        // xs4 reuse guard (also covers bs init)
            for (int idx = t; idx < ROWS_PER_CHUNK * 32; idx += 256) {
                int r = idx >> 5, oq = idx & 31;
                float4 v = make_float4(0.f, 0.f, 0.f, 0.f);
                if (r < mrows) v = x4[(size_t)bs[r] * (OBS / 4) + kq + oq];
                xs4[idx] = v;
            }
            __syncthreads();

            for (int oq = 0; oq < 32; ++oq) {
                float4 wq[8];
#pragma unroll
                for (int i = 0; i < 8; i++)
                    wq[i] = W4[(size_t)(ag + i * 32) * (OBS / 4) + kq + oq];
#pragma unroll
                for (int j = 0; j < 8; j++) {
                    float4 xq = xs4[(rg * 8 + j) * 32 + oq];
#pragma unroll
                    for (int i = 0; i < 8; i++) {
                        acc[j][i] = fmaf(xq.x, wq[i].x, acc[j][i]);
                        acc[j][i] = fmaf(xq.y, wq[i].y, acc[j][i]);
                        acc[j][i] = fmaf(xq.z, wq[i].z, acc[j][i]);
                        acc[j][i] = fmaf(xq.w, wq[i].w, acc[j][i]);
                    }
                }
            }
        }

        // scatter w*(dot + bias) into slot-indexed scratch (disjoint addresses -> deterministic)
#pragma unroll
        for (int j = 0; j < 8; j++) {
            int r = rg * 8 + j;
            if (r < mrows) {
                int   b = bs[r];
                int   sl = ss[r];
                float w = ws[r];
                float* dst = g_scr + ((size_t)(mat * 4 + sl) * BATCH + b) * ACT;
#pragma unroll
                for (int i = 0; i < 8; i++) {
                    int a = ag + i * 32;
                    dst[a] = w * (acc[j][i] + bias[a]);
                }
            }
        }
    }
}

// ---------------- kernel 3: combine slots, tanh squash, write output ----------------
__global__ void finalize_kernel(float* __restrict__ out) {
    const size_t N4 = (size_t)BATCH * ACT / 4;   // 1,048,576 float4 per matrix
    size_t i = (size_t)blockIdx.x * blockDim.x + threadIdx.x;
    if (i >= N4) return;

    const float4* s4 = (const float4*)g_scr;
    float4* out4 = (float4*)out;

    // mean = sum of slots 0..3
    float4 a0 = s4[0 * N4 + i], a1 = s4[1 * N4 + i], a2 = s4[2 * N4 + i], a3 = s4[3 * N4 + i];
    float4 mm;
    mm.x = a0.x + a1.x + a2.x + a3.x;
    mm.y = a0.y + a1.y + a2.y + a3.y;
    mm.z = a0.z + a1.z + a2.z + a3.z;
    mm.w = a0.w + a1.w + a2.w + a3.w;
    out4[i] = mm;

    // log_std = -5 + 3.5*(tanh(sum)+1)
    float4 b0 = s4[4 * N4 + i], b1 = s4[5 * N4 + i], b2 = s4[6 * N4 + i], b3 = s4[7 * N4 + i];
    float4 ll;
    ll.x = -5.f + 3.5f * (tanhf(b0.x + b1.x + b2.x + b3.x) + 1.f);
    ll.y = -5.f + 3.5f * (tanhf(b0.y + b1.y + b2.y + b3.y) + 1.f);
    ll.z = -5.f + 3.5f * (tanhf(b0.z + b1.z + b2.z + b3.z) + 1.f);
    ll.w = -5.f + 3.5f * (tanhf(b0.w + b1.w + b2.w + b3.w) + 1.f);
    out4[N4 + i] = ll;
}

// ---------------- launch ----------------
extern "C" void kernel_launch(void* const* d_in, const int* in_sizes, int n_in,
                              void* d_out, int out_size) {
    const float* x  = (const float*)d_in[0];
    const float* rw = (const float*)d_in[1];
    const float* rb = (const float*)d_in[2];
    const float* mw = (const float*)d_in[3];
    const float* mb = (const float*)d_in[4];
    const float* lw = (const float*)d_in[5];
    const float* lb = (const float*)d_in[6];
    float* out = (float*)d_out;

    void* cntp = nullptr;
    cudaGetSymbolAddress(&cntp, g_cnt);
    cudaMemsetAsync(cntp, 0, sizeof(int) * NE);

    router_kernel<<<BATCH / 4, 128>>>(x, rw, rb);

    dim3 g2(MAX_CHUNKS, NE);
    expert_kernel<<<g2, 256>>>(x, mw, mb, lw, lb);

    finalize_kernel<<<(BATCH * ACT / 4 + 255) / 256, 256>>>(out);
}

// round 3
// speedup vs baseline: 3.7318x; 3.7318x over previous
#include <cuda_runtime.h>
#include <cuda_bf16.h>
#include <math.h>
#include <cstdint>

#define BATCH 16384
#define OBS   512
#define ACT   256
#define NE    16
#define TOPK  4
#define TILE_M 128
#define KCHUNKS 16
#define MAX_CHUNKS (BATCH / TILE_M)   // 128 worst case per expert

// ---------------- static device scratch ----------------
__device__ int   g_cnt[NE];
__device__ int   g_ridx[NE * BATCH];   // packed b*4 + slot
__device__ float g_w[NE * BATCH];
__device__ float g_scr[(size_t)2 * 4 * BATCH * ACT];   // [mat][slot][BATCH][ACT]

// fp32 -> tf32 (round to nearest, keeps accuracy well under 1e-3)
__device__ __forceinline__ float f2tf32(float f) {
    uint32_t o;
    asm("cvt.rna.tf32.f32 %0, %1;" : "=r"(o) : "f"(f));
    return __uint_as_float(o);
}

// m16n8k8 tf32 mma (HMMA pipe; portable PTX, works on base sm_103 target)
__device__ __forceinline__ void mma_tf32(float* c,
                                         uint32_t a0, uint32_t a1, uint32_t a2, uint32_t a3,
                                         uint32_t b0, uint32_t b1) {
    asm volatile(
        "mma.sync.aligned.m16n8k8.row.col.f32.tf32.tf32.f32 "
        "{%0,%1,%2,%3}, {%4,%5,%6,%7}, {%8,%9}, {%0,%1,%2,%3};"
        : "+f"(c[0]), "+f"(c[1]), "+f"(c[2]), "+f"(c[3])
        : "r"(a0), "r"(a1), "r"(a2), "r"(a3), "r"(b0), "r"(b1));
}

// ---------------- kernel 1: router (2 rows per warp, float4 loads) ----------------
__global__ void router_kernel(const float* __restrict__ x,
                              const float* __restrict__ rw,
                              const float* __restrict__ rb) {
    const int warp = threadIdx.x >> 5;
    const int lane = threadIdx.x & 31;
    const int b0 = blockIdx.x * 8 + warp * 2;   // this warp handles rows b0, b0+1

    const float4* x4 = (const float4*)x;
    float4 xa[4], xb[4];
#pragma unroll
    for (int i = 0; i < 4; i++) {
        xa[i] = x4[(size_t)b0 * 128 + lane + 32 * i];
        xb[i] = x4[(size_t)(b0 + 1) * 128 + lane + 32 * i];
    }

    float l0 = 0.f, l1 = 0.f;   // lane e holds logit of expert e for rows 0/1
#pragma unroll
    for (int e = 0; e < NE; e++) {
        const float4* w4 = (const float4*)rw + e * 128;
        float s0 = 0.f, s1 = 0.f;
#pragma unroll
        for (int i = 0; i < 4; i++) {
            float4 w = w4[lane + 32 * i];
            s0 = fmaf(xa[i].x, w.x, fmaf(xa[i].y, w.y, fmaf(xa[i].z, w.z, fmaf(xa[i].w, w.w, s0))));
            s1 = fmaf(xb[i].x, w.x, fmaf(xb[i].y, w.y, fmaf(xb[i].z, w.z, fmaf(xb[i].w, w.w, s1))));
        }
#pragma unroll
        for (int off = 16; off; off >>= 1) {
            s0 += __shfl_xor_sync(0xffffffffu, s0, off);
            s1 += __shfl_xor_sync(0xffffffffu, s1, off);
        }
        if (lane == e) { l0 = s0 + rb[e]; l1 = s1 + rb[e]; }
    }

#pragma unroll
    for (int r = 0; r < 2; r++) {
        const int b = b0 + r;
        float v = (lane < NE) ? (r ? l1 : l0) : -1e30f;
        float m = v;
#pragma unroll
        for (int off = 16; off; off >>= 1) m = fmaxf(m, __shfl_xor_sync(0xffffffffu, m, off));
        float p = (lane < NE) ? expf(v - m) : 0.f;
        float s = p;
#pragma unroll
        for (int off = 16; off; off >>= 1) s += __shfl_xor_sync(0xffffffffu, s, off);
        float prob = p / s;

        float cur = (lane < NE) ? prob : -1.f;
#pragma unroll
        for (int slot = 0; slot < TOPK; slot++) {
            float mx = cur;
#pragma unroll
            for (int off = 16; off; off >>= 1) mx = fmaxf(mx, __shfl_xor_sync(0xffffffffu, mx, off));
            unsigned bal = __ballot_sync(0xffffffffu, cur == mx);
            int sel = __ffs(bal) - 1;
            if (lane == sel) {
                int pos = atomicAdd(&g_cnt[lane], 1);
                g_ridx[lane * BATCH + pos] = b * 4 + slot;
                g_w[lane * BATCH + pos]    = prob;
                cur = -1.f;
            }
        }
    }
}

// ---------------- kernel 2: grouped expert GEMM via mma.sync tf32 ----------------
// grid (row-chunk, expert, mat), 512 threads = 16 warps (4M x 4N), warp tile 32x64.
// K=512 in 16 chunks of 32 floats, double-buffered smem (stride 33 anti-conflict pad).
#define ASTRIDE 33
#define ABUF (TILE_M * ASTRIDE)     // 4224 floats
#define BBUF (ACT * ASTRIDE)        // 8448 floats
#define DYN_SMEM ((2 * ABUF + 2 * BBUF) * 4)   // 101376 bytes

__global__ void __launch_bounds__(512, 1)
expert_mma_kernel(const float* __restrict__ x,
                  const float* __restrict__ mw, const float* __restrict__ mb,
                  const float* __restrict__ lw, const float* __restrict__ lb) {
    const int e   = blockIdx.y;
    const int mat = blockIdx.z;
    const int n   = g_cnt[e];
    const int start = blockIdx.x * TILE_M;
    if (start >= n) return;
    const int mrows = min(TILE_M, n - start);

    __shared__ int   bs[TILE_M];
    __shared__ int   ss[TILE_M];
    __shared__ float ws[TILE_M];
    extern __shared__ float sm[];
    float* As = sm;                 // [2][ABUF]
    float* Bs = sm + 2 * ABUF;      // [2][BBUF]

    const int t = threadIdx.x;
    if (t < TILE_M) {
        if (t < mrows) {
            int entry = g_ridx[e * BATCH + start + t];
            bs[t] = entry >> 2; ss[t] = entry & 3;
            ws[t] = g_w[e * BATCH + start + t];
        } else { bs[t] = 0; ss[t] = 0; ws[t] = 0.f; }
    }
    __syncthreads();

    const float4* x4 = (const float4*)x;
    const float4* W4 = (const float4*)(mat ? lw : mw) + (size_t)e * ACT * (OBS / 4);

    const int lane = t & 31;
    const int g  = lane >> 2;       // group id 0..7
    const int tg = lane & 3;        // thread-in-group 0..3
    const int wid = t >> 5;
    const int wm = wid & 3;         // warp M tile (rows wm*32..)
    const int wn = wid >> 2;        // warp N tile (cols wn*64..)

    auto load_chunk = [&](int kc, int buf) {
        float* Ab = As + buf * ABUF;
#pragma unroll
        for (int i = 0; i < 2; i++) {               // A: 128 rows x 8 float4
            int idx = t + 512 * i;
            int r = idx >> 3, q = idx & 7;
            float4 v = make_float4(0.f, 0.f, 0.f, 0.f);
            if (r < mrows) v = x4[(size_t)bs[r] * (OBS / 4) + kc * 8 + q];
            float* p = Ab + r * ASTRIDE + q * 4;
            p[0] = f2tf32(v.x); p[1] = f2tf32(v.y); p[2] = f2tf32(v.z); p[3] = f2tf32(v.w);
        }
        float* Bb = Bs + buf * BBUF;
#pragma unroll
        for (int i = 0; i < 4; i++) {               // B: 256 rows x 8 float4
            int idx = t + 512 * i;
            int a = idx >> 3, q = idx & 7;
            float4 v = W4[(size_t)a * (OBS / 4) + kc * 8 + q];
            float* p = Bb + a * ASTRIDE + q * 4;
            p[0] = f2tf32(v.x); p[1] = f2tf32(v.y); p[2] = f2tf32(v.z); p[3] = f2tf32(v.w);
        }
    };

    float acc[2][8][4];
#pragma unroll
    for (int im = 0; im < 2; im++)
#pragma unroll
        for (int in = 0; in < 8; in++)
#pragma unroll
            for (int c = 0; c < 4; c++) acc[im][in][c] = 0.f;

    load_chunk(0, 0);
    __syncthreads();

    for (int kc = 0; kc < KCHUNKS; kc++) {
        const int buf = kc & 1;
        if (kc + 1 < KCHUNKS) load_chunk(kc + 1, buf ^ 1);

        const float* Abase = As + buf * ABUF + (wm * 32) * ASTRIDE;
        const float* Bbase = Bs + buf * BBUF + (wn * 64) * ASTRIDE;
#pragma unroll
        for (int ks = 0; ks < 4; ks++) {
            const int k0 = ks * 8;
            uint32_t a[2][4];
#pragma unroll
            for (int im = 0; im < 2; im++) {
                const float* ap = Abase + (im * 16 + g) * ASTRIDE + k0 + tg;
                a[im][0] = __float_as_uint(ap[0]);
                a[im][1] = __float_as_uint(ap[8 * ASTRIDE]);
                a[im][2] = __float_as_uint(ap[4]);
                a[im][3] = __float_as_uint(ap[8 * ASTRIDE + 4]);
            }
#pragma unroll
            for (int in = 0; in < 8; in++) {
                const float* bp = Bbase + (in * 8 + g) * ASTRIDE + k0 + tg;
                uint32_t b0 = __float_as_uint(bp[0]);
                uint32_t b1 = __float_as_uint(bp[4]);
                mma_tf32(acc[0][in], a[0][0], a[0][1], a[0][2], a[0][3], b0, b1);
                mma_tf32(acc[1][in], a[1][0], a[1][1], a[1][2], a[1][3], b0, b1);
            }
        }
        __syncthreads();
    }

    // epilogue: w * (acc + bias) -> slot-indexed scratch (deterministic)
    const float* bias = (mat ? lb : mb) + e * ACT;
    float2 bv[8];
#pragma unroll
    for (int in = 0; in < 8; in++) {
        int c = wn * 64 + in * 8 + 2 * tg;
        bv[in] = make_float2(__ldg(bias + c), __ldg(bias + c + 1));
    }
#pragma unroll
    for (int im = 0; im < 2; im++) {
#pragma unroll
        for (int half = 0; half < 2; half++) {
            int r = wm * 32 + im * 16 + half * 8 + g;
            if (r < mrows) {
                float w = ws[r];
                float* dst = g_scr + ((size_t)(mat * 4 + ss[r]) * BATCH + bs[r]) * ACT
                           + wn * 64 + 2 * tg;
#pragma unroll
                for (int in = 0; in < 8; in++) {
                    float2 v;
                    v.x = w * (acc[im][in][half * 2 + 0] + bv[in].x);
                    v.y = w * (acc[im][in][half * 2 + 1] + bv[in].y);
                    *(float2*)(dst + in * 8) = v;
                }
            }
        }
    }
}

// ---------------- kernel 3: combine slots, tanh squash ----------------
__global__ void finalize_kernel(float* __restrict__ out) {
    const size_t N4 = (size_t)BATCH * ACT / 4;
    size_t i = (size_t)blockIdx.x * blockDim.x + threadIdx.x;
    if (i >= N4) return;
    const float4* s4 = (const float4*)g_scr;
    float4* out4 = (float4*)out;

    float4 a0 = s4[0 * N4 + i], a1 = s4[1 * N4 + i], a2 = s4[2 * N4 + i], a3 = s4[3 * N4 + i];
    float4 mm;
    mm.x = a0.x + a1.x + a2.x + a3.x;
    mm.y = a0.y + a1.y + a2.y + a3.y;
    mm.z = a0.z + a1.z + a2.z + a3.z;
    mm.w = a0.w + a1.w + a2.w + a3.w;
    out4[i] = mm;

    float4 b0 = s4[4 * N4 + i], b1 = s4[5 * N4 + i], b2 = s4[6 * N4 + i], b3 = s4[7 * N4 + i];
    float4 ll;
    ll.x = -5.f + 3.5f * (tanhf(b0.x + b1.x + b2.x + b3.x) + 1.f);
    ll.y = -5.f + 3.5f * (tanhf(b0.y + b1.y + b2.y + b3.y) + 1.f);
    ll.z = -5.f + 3.5f * (tanhf(b0.z + b1.z + b2.z + b3.z) + 1.f);
    ll.w = -5.f + 3.5f * (tanhf(b0.w + b1.w + b2.w + b3.w) + 1.f);
    out4[N4 + i] = ll;
}

// ---------------- launch ----------------
extern "C" void kernel_launch(void* const* d_in, const int* in_sizes, int n_in,
                              void* d_out, int out_size) {
    const float* x  = (const float*)d_in[0];
    const float* rw = (const float*)d_in[1];
    const float* rb = (const float*)d_in[2];
    const float* mw = (const float*)d_in[3];
    const float* mb = (const float*)d_in[4];
    const float* lw = (const float*)d_in[5];
    const float* lb = (const float*)d_in[6];
    float* out = (float*)d_out;

    cudaFuncSetAttribute(expert_mma_kernel,
                         cudaFuncAttributeMaxDynamicSharedMemorySize, DYN_SMEM);

    void* cntp = nullptr;
    cudaGetSymbolAddress(&cntp, g_cnt);
    cudaMemsetAsync(cntp, 0, sizeof(int) * NE);

    router_kernel<<<BATCH / 8, 128>>>(x, rw, rb);

    dim3 g2(MAX_CHUNKS, NE, 2);
    expert_mma_kernel<<<g2, 512, DYN_SMEM>>>(x, mw, mb, lw, lb);

    finalize_kernel<<<(BATCH * ACT / 4 + 255) / 256, 256>>>(out);
}

// round 4
// speedup vs baseline: 6.0195x; 1.6130x over previous
#include <cuda_runtime.h>
#include <cuda_bf16.h>
#include <math.h>
#include <cstdint>

#define BATCH 16384
#define OBS   512
#define ACT   256
#define NE    16
#define TOPK  4
#define TILE_M 128
#define NCHUNK 8                       // K chunks of 64
#define MAX_CHUNKS (BATCH / TILE_M)    // 128 worst case per expert

// ---------------- static device scratch ----------------
__device__ int   g_cnt[NE];
__device__ int   g_ridx[NE * BATCH];   // packed b*4 + slot
__device__ float g_w[NE * BATCH];
__device__ float g_scr[(size_t)2 * 4 * BATCH * ACT];   // [mat][slot][BATCH][ACT]

// fp32 -> tf32 RNA (unbiased rounding; keeps error well under 1e-3)
__device__ __forceinline__ float f2tf32(float f) {
    uint32_t o;
    asm("cvt.rna.tf32.f32 %0, %1;" : "=r"(o) : "f"(f));
    return __uint_as_float(o);
}
__device__ __forceinline__ float4 cvt4(float4 v) {
    return make_float4(f2tf32(v.x), f2tf32(v.y), f2tf32(v.z), f2tf32(v.w));
}

// m16n8k8 tf32 mma (HMMA pipe, portable PTX on base sm_103)
__device__ __forceinline__ void mma_tf32(float* c,
                                         uint32_t a0, uint32_t a1, uint32_t a2, uint32_t a3,
                                         uint32_t b0, uint32_t b1) {
    asm volatile(
        "mma.sync.aligned.m16n8k8.row.col.f32.tf32.tf32.f32 "
        "{%0,%1,%2,%3}, {%4,%5,%6,%7}, {%8,%9}, {%0,%1,%2,%3};"
        : "+f"(c[0]), "+f"(c[1]), "+f"(c[2]), "+f"(c[3])
        : "r"(a0), "r"(a1), "r"(a2), "r"(a3), "r"(b0), "r"(b1));
}

// XOR swizzle on float4 column index (row stride = 16 float4)
__device__ __forceinline__ int swz(int c, int r) { return (c & 8) | ((c ^ r) & 7); }

// ---------------- kernel 1: router (1 row per warp) ----------------
__global__ void __launch_bounds__(128) router_kernel(const float* __restrict__ x,
                                                     const float* __restrict__ rw,
                                                     const float* __restrict__ rb) {
    const int warp = threadIdx.x >> 5;
    const int lane = threadIdx.x & 31;
    const int b = blockIdx.x * 4 + warp;

    const float4* x4 = (const float4*)x;
    float4 xa[4];
#pragma unroll
    for (int i = 0; i < 4; i++) xa[i] = x4[(size_t)b * 128 + lane + 32 * i];

    float logit = 0.f;
#pragma unroll
    for (int e = 0; e < NE; e++) {
        const float4* w4 = (const float4*)rw + e * 128;
        float s = 0.f;
#pragma unroll
        for (int i = 0; i < 4; i++) {
            float4 w = __ldg(w4 + lane + 32 * i);
            s = fmaf(xa[i].x, w.x, fmaf(xa[i].y, w.y, fmaf(xa[i].z, w.z, fmaf(xa[i].w, w.w, s))));
        }
#pragma unroll
        for (int off = 16; off; off >>= 1) s += __shfl_xor_sync(0xffffffffu, s, off);
        if (lane == e) logit = s + rb[e];
    }

    float v = (lane < NE) ? logit : -1e30f;
    float m = v;
#pragma unroll
    for (int off = 16; off; off >>= 1) m = fmaxf(m, __shfl_xor_sync(0xffffffffu, m, off));
    float p = (lane < NE) ? expf(v - m) : 0.f;
    float s = p;
#pragma unroll
    for (int off = 16; off; off >>= 1) s += __shfl_xor_sync(0xffffffffu, s, off);
    float prob = p / s;

    float cur = (lane < NE) ? prob : -1.f;
#pragma unroll
    for (int slot = 0; slot < TOPK; slot++) {
        float mx = cur;
#pragma unroll
        for (int off = 16; off; off >>= 1) mx = fmaxf(mx, __shfl_xor_sync(0xffffffffu, mx, off));
        unsigned bal = __ballot_sync(0xffffffffu, cur == mx);
        int sel = __ffs(bal) - 1;
        if (lane == sel) {
            int pos = atomicAdd(&g_cnt[lane], 1);
            g_ridx[lane * BATCH + pos] = b * 4 + slot;
            g_w[lane * BATCH + pos]    = prob;
            cur = -1.f;
        }
    }
}

// ---------------- kernel 2: pipelined tf32 mma grouped GEMM ----------------
#define AF (TILE_M * 64)   // 8192 floats per A buffer (32 KB)
#define BF (ACT * 64)      // 16384 floats per B buffer (64 KB)
#define DYN_SMEM (2 * (AF + BF) * 4)   // 196608 bytes

__global__ void __launch_bounds__(512, 1)
expert_mma_kernel(const float* __restrict__ x,
                  const float* __restrict__ mw, const float* __restrict__ mb,
                  const float* __restrict__ lw, const float* __restrict__ lb) {
    const int e   = blockIdx.y;
    const int mat = blockIdx.z;
    const int n   = g_cnt[e];
    const int start = blockIdx.x * TILE_M;
    if (start >= n) return;
    const int mrows = min(TILE_M, n - start);

    __shared__ int   bs[TILE_M];
    __shared__ int   ss[TILE_M];
    __shared__ float ws[TILE_M];
    extern __shared__ float sm[];
    float* As = sm;              // [2][AF]
    float* Bs = sm + 2 * AF;     // [2][BF]

    const int t = threadIdx.x;
    if (t < TILE_M) {
        if (t < mrows) {
            int entry = g_ridx[e * BATCH + start + t];
            bs[t] = entry >> 2; ss[t] = entry & 3;
            ws[t] = g_w[e * BATCH + start + t];
        } else { bs[t] = 0; ss[t] = 0; ws[t] = 0.f; }
    }
    __syncthreads();

    const float4* x4 = (const float4*)x;
    const float4* W4 = (const float4*)(mat ? lw : mw) + (size_t)e * ACT * (OBS / 4);

    const int lane = t & 31;
    const int g  = lane >> 2;
    const int tg = lane & 3;
    const int wid = t >> 5;
    const int wm = wid & 3;     // warp M tile (rows wm*32..)
    const int wn = wid >> 2;    // warp N tile (cols wn*64..)

    float4 sa[2], sb[4];        // half-chunk staging (24 regs)

    auto loadA = [&](int kc, int half) {
#pragma unroll
        for (int i = 0; i < 2; i++) {
            int p = t + 512 * i, r = p >> 3, c = (p & 7) + half * 8;
            sa[i] = (r < mrows) ? x4[(size_t)bs[r] * 128 + kc * 16 + c]
                                : make_float4(0.f, 0.f, 0.f, 0.f);
        }
    };
    auto loadB = [&](int kc, int half) {
#pragma unroll
        for (int i = 0; i < 4; i++) {
            int p = t + 512 * i, r = p >> 3, c = (p & 7) + half * 8;
            sb[i] = W4[(size_t)r * 128 + kc * 16 + c];
        }
    };
    auto storeA = [&](int buf, int half) {
        float* Ab = As + buf * AF;
#pragma unroll
        for (int i = 0; i < 2; i++) {
            int p = t + 512 * i, r = p >> 3, c = (p & 7) + half * 8;
            *(float4*)(Ab + (r * 16 + swz(c, r)) * 4) = cvt4(sa[i]);
        }
    };
    auto storeB = [&](int buf, int half) {
        float* Bb = Bs + buf * BF;
#pragma unroll
        for (int i = 0; i < 4; i++) {
            int p = t + 512 * i, r = p >> 3, c = (p & 7) + half * 8;
            *(float4*)(Bb + (r * 16 + swz(c, r)) * 4) = cvt4(sb[i]);
        }
    };

    float acc[2][8][4];
#pragma unroll
    for (int im = 0; im < 2; im++)
#pragma unroll
        for (int in = 0; in < 8; in++)
#pragma unroll
            for (int c = 0; c < 4; c++) acc[im][in][c] = 0.f;

    // prologue: fill buffer 0
    loadA(0, 0); loadB(0, 0); storeA(0, 0); storeB(0, 0);
    loadA(0, 1); loadB(0, 1); storeA(0, 1); storeB(0, 1);
    __syncthreads();

#pragma unroll
    for (int kc = 0; kc < NCHUNK; kc++) {
        const int buf = kc & 1;
        const float* Ab = As + buf * AF + (wm * 32) * 64;
        const float* Bb = Bs + buf * BF + (wn * 64) * 64;
        const bool pre = (kc + 1 < NCHUNK);

        if (pre) { loadA(kc + 1, 0); loadB(kc + 1, 0); }

        // ks 0..3 (reads columns 0..31 of buf)
#pragma unroll
        for (int ks = 0; ks < 4; ks++) {
            const int c0 = 2 * ks, c1 = 2 * ks + 1;
            uint32_t a[2][4];
#pragma unroll
            for (int im = 0; im < 2; im++) {
                const int row = im * 16 + g;
                const float* ap = Ab + row * 64;
                const int s0 = swz(c0, row) * 4 + tg;
                const int s1 = swz(c1, row) * 4 + tg;
                a[im][0] = __float_as_uint(ap[s0]);
                a[im][1] = __float_as_uint(ap[512 + s0]);
                a[im][2] = __float_as_uint(ap[s1]);
                a[im][3] = __float_as_uint(ap[512 + s1]);
            }
#pragma unroll
            for (int in = 0; in < 8; in++) {
                const int rn = in * 8 + g;
                const float* bp = Bb + rn * 64;
                uint32_t b0 = __float_as_uint(bp[swz(c0, rn) * 4 + tg]);
                uint32_t b1 = __float_as_uint(bp[swz(c1, rn) * 4 + tg]);
                mma_tf32(acc[0][in], a[0][0], a[0][1], a[0][2], a[0][3], b0, b1);
                mma_tf32(acc[1][in], a[1][0], a[1][1], a[1][2], a[1][3], b0, b1);
            }
        }

        if (pre) { storeA(buf ^ 1, 0); storeB(buf ^ 1, 0); loadA(kc + 1, 1); loadB(kc + 1, 1); }

        // ks 4..7 (reads columns 32..63 of buf)
#pragma unroll
        for (int ks = 4; ks < 8; ks++) {
            const int c0 = 2 * ks, c1 = 2 * ks + 1;
            uint32_t a[2][4];
#pragma unroll
            for (int im = 0; im < 2; im++) {
                const int row = im * 16 + g;
                const float* ap = Ab + row * 64;
                const int s0 = swz(c0, row) * 4 + tg;
                const int s1 = swz(c1, row) * 4 + tg;
                a[im][0] = __float_as_uint(ap[s0]);
                a[im][1] = __float_as_uint(ap[512 + s0]);
                a[im][2] = __float_as_uint(ap[s1]);
                a[im][3] = __float_as_uint(ap[512 + s1]);
            }
#pragma unroll
            for (int in = 0; in < 8; in++) {
                const int rn = in * 8 + g;
                const float* bp = Bb + rn * 64;
                uint32_t b0 = __float_as_uint(bp[swz(c0, rn) * 4 + tg]);
                uint32_t b1 = __float_as_uint(bp[swz(c1, rn) * 4 + tg]);
                mma_tf32(acc[0][in], a[0][0], a[0][1], a[0][2], a[0][3], b0, b1);
                mma_tf32(acc[1][in], a[1][0], a[1][1], a[1][2], a[1][3], b0, b1);
            }
        }

        if (pre) { storeA(buf ^ 1, 1); storeB(buf ^ 1, 1); }
        __syncthreads();
    }

    // epilogue: w * (acc + bias) -> slot-indexed scratch (deterministic)
    const float* bias = (mat ? lb : mb) + e * ACT;
    float2 bv[8];
#pragma unroll
    for (int in = 0; in < 8; in++) {
        int c = wn * 64 + in * 8 + 2 * tg;
        bv[in] = make_float2(__ldg(bias + c), __ldg(bias + c + 1));
    }
#pragma unroll
    for (int im = 0; im < 2; im++) {
#pragma unroll
        for (int half = 0; half < 2; half++) {
            int r = wm * 32 + im * 16 + half * 8 + g;
            if (r < mrows) {
                float w = ws[r];
                float* dst = g_scr + ((size_t)(mat * 4 + ss[r]) * BATCH + bs[r]) * ACT
                           + wn * 64 + 2 * tg;
#pragma unroll
                for (int in = 0; in < 8; in++) {
                    float2 v;
                    v.x = w * (acc[im][in][half * 2 + 0] + bv[in].x);
                    v.y = w * (acc[im][in][half * 2 + 1] + bv[in].y);
                    *(float2*)(dst + in * 8) = v;
                }
            }
        }
    }
}

// ---------------- kernel 3: combine slots, tanh squash ----------------
__global__ void finalize_kernel(float* __restrict__ out) {
    const size_t N4 = (size_t)BATCH * ACT / 4;
    size_t i = (size_t)blockIdx.x * blockDim.x + threadIdx.x;
    if (i >= N4) return;
    const float4* s4 = (const float4*)g_scr;
    float4* out4 = (float4*)out;

    float4 a0 = s4[0 * N4 + i], a1 = s4[1 * N4 + i], a2 = s4[2 * N4 + i], a3 = s4[3 * N4 + i];
    float4 mm;
    mm.x = a0.x + a1.x + a2.x + a3.x;
    mm.y = a0.y + a1.y + a2.y + a3.y;
    mm.z = a0.z + a1.z + a2.z + a3.z;
    mm.w = a0.w + a1.w + a2.w + a3.w;
    out4[i] = mm;

    float4 b0 = s4[4 * N4 + i], b1 = s4[5 * N4 + i], b2 = s4[6 * N4 + i], b3 = s4[7 * N4 + i];
    float4 ll;
    ll.x = -5.f + 3.5f * (tanhf(b0.x + b1.x + b2.x + b3.x) + 1.f);
    ll.y = -5.f + 3.5f * (tanhf(b0.y + b1.y + b2.y + b3.y) + 1.f);
    ll.z = -5.f + 3.5f * (tanhf(b0.z + b1.z + b2.z + b3.z) + 1.f);
    ll.w = -5.f + 3.5f * (tanhf(b0.w + b1.w + b2.w + b3.w) + 1.f);
    out4[N4 + i] = ll;
}

// ---------------- launch ----------------
extern "C" void kernel_launch(void* const* d_in, const int* in_sizes, int n_in,
                              void* d_out, int out_size) {
    const float* x  = (const float*)d_in[0];
    const float* rw = (const float*)d_in[1];
    const float* rb = (const float*)d_in[2];
    const float* mw = (const float*)d_in[3];
    const float* mb = (const float*)d_in[4];
    const float* lw = (const float*)d_in[5];
    const float* lb = (const float*)d_in[6];
    float* out = (float*)d_out;

    cudaFuncSetAttribute(expert_mma_kernel,
                         cudaFuncAttributeMaxDynamicSharedMemorySize, DYN_SMEM);

    void* cntp = nullptr;
    cudaGetSymbolAddress(&cntp, g_cnt);
    cudaMemsetAsync(cntp, 0, sizeof(int) * NE);

    router_kernel<<<BATCH / 4, 128>>>(x, rw, rb);

    dim3 g2(MAX_CHUNKS, NE, 2);
    expert_mma_kernel<<<g2, 512, DYN_SMEM>>>(x, mw, mb, lw, lb);

    finalize_kernel<<<(BATCH * ACT / 4 + 255) / 256, 256>>>(out);
}

// round 5
// speedup vs baseline: 6.1904x; 1.0284x over previous
#include <cuda_runtime.h>
#include <cuda_bf16.h>
#include <math.h>
#include <cstdint>

#define BATCH 16384
#define OBS   512
#define ACT   256
#define NE    16
#define TOPK  4
#define TILE_M 128
#define NCHUNK 8                       // K chunks of 64
#define MAX_CHUNKS (BATCH / TILE_M)    // 128 worst case per expert

// ---------------- static device scratch ----------------
__device__ int   g_cnt[NE];
__device__ int   g_ridx[NE * BATCH];   // packed b*4 + slot
__device__ float g_w[NE * BATCH];
__device__ float g_scr[(size_t)2 * 4 * BATCH * ACT];   // [mat][slot][BATCH][ACT]
__device__ float g_xt[(size_t)BATCH * OBS];            // tf32, k-permuted x
__device__ float g_wt[(size_t)2 * NE * ACT * OBS];     // tf32, k-permuted weights

// fp32 -> tf32 RNA
__device__ __forceinline__ float f2tf32(float f) {
    uint32_t o;
    asm("cvt.rna.tf32.f32 %0, %1;" : "=r"(o) : "f"(f));
    return __uint_as_float(o);
}

// m16n8k8 tf32 mma
__device__ __forceinline__ void mma_tf32(float* c,
                                         uint32_t a0, uint32_t a1, uint32_t a2, uint32_t a3,
                                         uint32_t b0, uint32_t b1) {
    asm volatile(
        "mma.sync.aligned.m16n8k8.row.col.f32.tf32.tf32.f32 "
        "{%0,%1,%2,%3}, {%4,%5,%6,%7}, {%8,%9}, {%0,%1,%2,%3};"
        : "+f"(c[0]), "+f"(c[1]), "+f"(c[2]), "+f"(c[3])
        : "r"(a0), "r"(a1), "r"(a2), "r"(a3), "r"(b0), "r"(b1));
}

__device__ __forceinline__ uint32_t smem_u32(const void* p) {
    uint32_t a;
    asm("{ .reg .u64 t; cvta.to.shared.u64 t, %1; cvt.u32.u64 %0, t; }" : "=r"(a) : "l"(p));
    return a;
}
__device__ __forceinline__ void cp16(uint32_t dst, const void* src, int sz) {
    asm volatile("cp.async.cg.shared.global [%0], [%1], 16, %2;"
                 :: "r"(dst), "l"(src), "r"(sz) : "memory");
}
#define CP_COMMIT() asm volatile("cp.async.commit_group;" ::: "memory")
#define CP_WAIT0()  asm volatile("cp.async.wait_group 0;" ::: "memory")

// ---------------- kernel 0: weight pre-convert (tf32 + k-permute) ----------------
// permuted group order: [k0,k4,k1,k5, k2,k6,k3,k7]
__global__ void __launch_bounds__(256) wconv_kernel(const float* __restrict__ mw,
                                                    const float* __restrict__ lw) {
    int flat = blockIdx.x * 256 + threadIdx.x;   // 2*16*256*64 = 524288 groups
    int g = flat & 63;
    int rowp = flat >> 6;                        // 0..8191
    int mat = rowp >> 12;
    const float4* s4 = (const float4*)((mat ? lw : mw) + (size_t)(rowp & 4095) * OBS + g * 8);
    float4 v0 = s4[0], v1 = s4[1];
    float4 q0 = make_float4(f2tf32(v0.x), f2tf32(v1.x), f2tf32(v0.y), f2tf32(v1.y));
    float4 q1 = make_float4(f2tf32(v0.z), f2tf32(v1.z), f2tf32(v0.w), f2tf32(v1.w));
    float4* d4 = (float4*)(g_wt + (size_t)rowp * OBS + g * 8);
    d4[0] = q0; d4[1] = q1;
}

// ---------------- kernel 1: router + x pre-convert ----------------
__global__ void __launch_bounds__(128) router_kernel(const float* __restrict__ x,
                                                     const float* __restrict__ rw,
                                                     const float* __restrict__ rb) {
    const int warp = threadIdx.x >> 5;
    const int lane = threadIdx.x & 31;
    const int b = blockIdx.x * 4 + warp;

    // lane handles k-groups 2*lane, 2*lane+1  (k = 16*lane .. 16*lane+15)
    const float4* x4 = (const float4*)x + (size_t)b * 128;
    float4 v[4];
#pragma unroll
    for (int i = 0; i < 4; i++) v[i] = x4[4 * lane + i];

    // write permuted tf32 x
    {
        float4* d4 = (float4*)(g_xt + (size_t)b * OBS) + 4 * lane;
        d4[0] = make_float4(f2tf32(v[0].x), f2tf32(v[1].x), f2tf32(v[0].y), f2tf32(v[1].y));
        d4[1] = make_float4(f2tf32(v[0].z), f2tf32(v[1].z), f2tf32(v[0].w), f2tf32(v[1].w));
        d4[2] = make_float4(f2tf32(v[2].x), f2tf32(v[3].x), f2tf32(v[2].y), f2tf32(v[3].y));
        d4[3] = make_float4(f2tf32(v[2].z), f2tf32(v[3].z), f2tf32(v[2].w), f2tf32(v[3].w));
    }

    // partial logits: 16 parallel accumulators per lane
    float s[16];
#pragma unroll
    for (int e = 0; e < NE; e++) {
        const float4* w4 = (const float4*)rw + e * 128 + 4 * lane;
        float a = 0.f;
#pragma unroll
        for (int i = 0; i < 4; i++) {
            float4 w = __ldg(w4 + i);
            a = fmaf(v[i].x, w.x, fmaf(v[i].y, w.y, fmaf(v[i].z, w.z, fmaf(v[i].w, w.w, a))));
        }
        s[e] = a;
    }

    // register-folding butterfly: 16 regs over 32 lanes -> 1 reg, expert = (lane>>1)&15
#pragma unroll
    for (int round = 0; round < 4; round++) {
        const int bit = 16 >> round;       // 16,8,4,2
        const int nreg = 8 >> round;       // 8,4,2,1
        bool hi = (lane & bit) != 0;
#pragma unroll
        for (int e = 0; e < 8; e++) {
            if (e < nreg) {
                float send = hi ? s[e] : s[e + nreg];
                float recv = __shfl_xor_sync(0xffffffffu, send, bit);
                float keep = hi ? s[e + nreg] : s[e];
                s[e] = keep + recv;
            }
        }
    }
    float lsum = s[0] + __shfl_xor_sync(0xffffffffu, s[0], 1);
    const int my_e = (lane >> 1) & 15;
    float logit = lsum + __ldg(rb + my_e);

    // softmax over 16 experts (each held by a lane pair; even lane canonical for sums)
    float m = logit;
#pragma unroll
    for (int off = 16; off; off >>= 1) m = fmaxf(m, __shfl_xor_sync(0xffffffffu, m, off));
    float pexp = expf(logit - m);
    float pc = (lane & 1) ? 0.f : pexp;
#pragma unroll
    for (int off = 16; off; off >>= 1) pc += __shfl_xor_sync(0xffffffffu, pc, off);
    float prob_pair = pexp / pc;
    // move to layout: lane e (0..15) holds prob[e]
    float prob = __shfl_sync(0xffffffffu, prob_pair, 2 * (lane & 15));

    float cur = (lane < NE) ? prob : -1.f;
#pragma unroll
    for (int slot = 0; slot < TOPK; slot++) {
        float mx = cur;
#pragma unroll
        for (int off = 16; off; off >>= 1) mx = fmaxf(mx, __shfl_xor_sync(0xffffffffu, mx, off));
        unsigned bal = __ballot_sync(0xffffffffu, cur == mx);
        int sel = __ffs(bal) - 1;
        if (lane == sel) {
            int pos = atomicAdd(&g_cnt[lane], 1);
            g_ridx[lane * BATCH + pos] = b * 4 + slot;
            g_w[lane * BATCH + pos]    = prob;
            cur = -1.f;
        }
    }
}

// ---------------- kernel 2: cp.async-pipelined tf32 mma grouped GEMM ----------------
#define ABYTES 32768u                  // 128 rows x 16 quads x 16B
#define BBYTES 65536u                  // 256 rows x 16 quads x 16B
#define DYN_SMEM (2 * (ABYTES + BBYTES))   // 196608

__global__ void __launch_bounds__(512, 1)
expert_mma_kernel(const float* __restrict__ mb, const float* __restrict__ lb) {
    const int e   = blockIdx.y;
    const int mat = blockIdx.z;
    const int n   = g_cnt[e];
    const int start = blockIdx.x * TILE_M;
    if (start >= n) return;
    const int mrows = min(TILE_M, n - start);

    __shared__ int   bs[TILE_M];
    __shared__ int   ss[TILE_M];
    __shared__ float ws[TILE_M];
    extern __shared__ char smraw[];
    const uint32_t sb = smem_u32(smraw);

    const int t = threadIdx.x;
    if (t < TILE_M) {
        if (t < mrows) {
            int entry = g_ridx[e * BATCH + start + t];
            bs[t] = entry >> 2; ss[t] = entry & 3;
            ws[t] = g_w[e * BATCH + start + t];
        } else { bs[t] = 0; ss[t] = 0; ws[t] = 0.f; }
    }
    __syncthreads();

    const float* xt = g_xt;
    const float* wt = g_wt + (size_t)((mat * NE + e) * ACT) * OBS;

    const int lane = t & 31;
    const int g  = lane >> 2;
    const int tg = lane & 3;
    const int wid = t >> 5;
    const int wm = wid & 3;     // warp M tile (rows wm*32..)
    const int wn = wid >> 2;    // warp N tile (cols wn*64..)

    // issue one K-chunk (64 k) of cp.asyncs into buffer buf
    auto issue = [&](int kc, int buf) {
        const uint32_t abase = sb + buf * ABYTES;
#pragma unroll
        for (int i = 0; i < 4; i++) {               // A: 2048 quads
            int idx = t + 512 * i;
            int r = idx >> 4, q = idx & 15;
            const float* src = xt + (size_t)bs[r] * OBS + kc * 64 + q * 4;
            uint32_t d = abase + (uint32_t)(r * 16 + (q ^ ((r & 7) << 1))) * 16u;
            cp16(d, src, (r < mrows) ? 16 : 0);
        }
        const uint32_t bbase = sb + 2 * ABYTES + buf * BBYTES;
#pragma unroll
        for (int i = 0; i < 8; i++) {               // B: 4096 quads
            int idx = t + 512 * i;
            int r = idx >> 4, q = idx & 15;
            const float* src = wt + (size_t)r * OBS + kc * 64 + q * 4;
            cp16(bbase + (uint32_t)(r * 16 + (q ^ ((r & 7) << 1))) * 16u, src, 16);
        }
    };

    float acc[2][8][4];
#pragma unroll
    for (int im = 0; im < 2; im++)
#pragma unroll
        for (int in = 0; in < 8; in++)
#pragma unroll
            for (int c = 0; c < 4; c++) acc[im][in][c] = 0.f;

    issue(0, 0);
    CP_COMMIT();

#pragma unroll 1
    for (int kc = 0; kc < NCHUNK; kc++) {
        const int buf = kc & 1;
        CP_WAIT0();
        __syncthreads();
        if (kc + 1 < NCHUNK) { issue(kc + 1, buf ^ 1); CP_COMMIT(); }

        const float2* A2 = (const float2*)(smraw + buf * ABYTES);
        const float2* B2 = (const float2*)(smraw + 2 * ABYTES + buf * BBYTES);
        const float2* Aw = A2 + (size_t)(wm * 32) * 32;
        const float2* Bw = B2 + (size_t)(wn * 64) * 32;
        const int swA = (g & 7) << 2;   // rows' &7 == g for both im and +8

#pragma unroll
        for (int ks = 0; ks < 8; ks++) {
            const int fidx = (ks * 4 + tg) ^ swA;
            uint32_t a[2][4];
#pragma unroll
            for (int im = 0; im < 2; im++) {
                const float2* ap = Aw + (size_t)(im * 16 + g) * 32;
                float2 lo = ap[fidx];
                float2 hi = ap[8 * 32 + fidx];
                a[im][0] = __float_as_uint(lo.x);
                a[im][1] = __float_as_uint(hi.x);
                a[im][2] = __float_as_uint(lo.y);
                a[im][3] = __float_as_uint(hi.y);
            }
#pragma unroll
            for (int in = 0; in < 8; in++) {
                float2 bf = Bw[(size_t)(in * 8 + g) * 32 + fidx];
                uint32_t b0 = __float_as_uint(bf.x);
                uint32_t b1 = __float_as_uint(bf.y);
                mma_tf32(acc[0][in], a[0][0], a[0][1], a[0][2], a[0][3], b0, b1);
                mma_tf32(acc[1][in], a[1][0], a[1][1], a[1][2], a[1][3], b0, b1);
            }
        }
        __syncthreads();
    }

    // epilogue: w * (acc + bias) -> slot-indexed scratch (deterministic)
    const float* bias = (mat ? lb : mb) + e * ACT;
    float2 bv[8];
#pragma unroll
    for (int in = 0; in < 8; in++) {
        int c = wn * 64 + in * 8 + 2 * tg;
        bv[in] = make_float2(__ldg(bias + c), __ldg(bias + c + 1));
    }
#pragma unroll
    for (int im = 0; im < 2; im++) {
#pragma unroll
        for (int half = 0; half < 2; half++) {
            int r = wm * 32 + im * 16 + half * 8 + g;
            if (r < mrows) {
                float w = ws[r];
                float* dst = g_scr + ((size_t)(mat * 4 + ss[r]) * BATCH + bs[r]) * ACT
                           + wn * 64 + 2 * tg;
#pragma unroll
                for (int in = 0; in < 8; in++) {
                    float2 o;
                    o.x = w * (acc[im][in][half * 2 + 0] + bv[in].x);
                    o.y = w * (acc[im][in][half * 2 + 1] + bv[in].y);
                    *(float2*)(dst + in * 8) = o;
                }
            }
        }
    }
}

// ---------------- kernel 3: combine slots, tanh squash ----------------
__global__ void finalize_kernel(float* __restrict__ out) {
    const size_t N4 = (size_t)BATCH * ACT / 4;
    size_t i = (size_t)blockIdx.x * blockDim.x + threadIdx.x;
    if (i >= N4) return;
    const float4* s4 = (const float4*)g_scr;
    float4* out4 = (float4*)out;

    float4 a0 = s4[0 * N4 + i], a1 = s4[1 * N4 + i], a2 = s4[2 * N4 + i], a3 = s4[3 * N4 + i];
    float4 mm;
    mm.x = a0.x + a1.x + a2.x + a3.x;
    mm.y = a0.y + a1.y + a2.y + a3.y;
    mm.z = a0.z + a1.z + a2.z + a3.z;
    mm.w = a0.w + a1.w + a2.w + a3.w;
    out4[i] = mm;

    float4 b0 = s4[4 * N4 + i], b1 = s4[5 * N4 + i], b2 = s4[6 * N4 + i], b3 = s4[7 * N4 + i];
    float4 ll;
    ll.x = -5.f + 3.5f * (tanhf(b0.x + b1.x + b2.x + b3.x) + 1.f);
    ll.y = -5.f + 3.5f * (tanhf(b0.y + b1.y + b2.y + b3.y) + 1.f);
    ll.z = -5.f + 3.5f * (tanhf(b0.z + b1.z + b2.z + b3.z) + 1.f);
    ll.w = -5.f + 3.5f * (tanhf(b0.w + b1.w + b2.w + b3.w) + 1.f);
    out4[N4 + i] = ll;
}

// ---------------- launch ----------------
extern "C" void kernel_launch(void* const* d_in, const int* in_sizes, int n_in,
                              void* d_out, int out_size) {
    const float* x  = (const float*)d_in[0];
    const float* rw = (const float*)d_in[1];
    const float* rb = (const float*)d_in[2];
    const float* mw = (const float*)d_in[3];
    const float* mb = (const float*)d_in[4];
    const float* lw = (const float*)d_in[5];
    const float* lb = (const float*)d_in[6];
    float* out = (float*)d_out;

    cudaFuncSetAttribute(expert_mma_kernel,
                         cudaFuncAttributeMaxDynamicSharedMemorySize, DYN_SMEM);

    void* cntp = nullptr;
    cudaGetSymbolAddress(&cntp, g_cnt);
    cudaMemsetAsync(cntp, 0, sizeof(int) * NE);

    wconv_kernel<<<2048, 256>>>(mw, lw);
    router_kernel<<<BATCH / 4, 128>>>(x, rw, rb);

    dim3 g2(MAX_CHUNKS, NE, 2);
    expert_mma_kernel<<<g2, 512, DYN_SMEM>>>(mb, lb);

    finalize_kernel<<<(BATCH * ACT / 4 + 255) / 256, 256>>>(out);
}

// round 6
// speedup vs baseline: 8.0870x; 1.3064x over previous
#include <cuda_runtime.h>
#include <cuda_fp16.h>
#include <math.h>
#include <cstdint>

#define BATCH 16384
#define OBS   512
#define ACT   256
#define NE    16
#define TOPK  4
#define TILE_M 128
#define NCHUNK 4                       // K chunks of 128
#define MAX_CHUNKS (BATCH / TILE_M)

// ---------------- static device scratch ----------------
__device__ int    g_cnt[NE];
__device__ int    g_ridx[NE * BATCH];
__device__ float  g_w[NE * BATCH];
__device__ float  g_scr[(size_t)2 * 4 * BATCH * ACT];     // [mat][slot][BATCH][ACT]
__device__ __half g_xt[(size_t)BATCH * OBS];              // fp16, k-permuted x
__device__ __half g_wt[(size_t)2 * NE * ACT * OBS];       // fp16, k-permuted weights

struct alignas(16) H8 { __half2 a, b, c, d; };

// m16n8k16 fp16 mma, fp32 accumulate
__device__ __forceinline__ void mma_f16(float* c,
                                        uint32_t a0, uint32_t a1, uint32_t a2, uint32_t a3,
                                        uint32_t b0, uint32_t b1) {
    asm volatile(
        "mma.sync.aligned.m16n8k16.row.col.f32.f16.f16.f32 "
        "{%0,%1,%2,%3}, {%4,%5,%6,%7}, {%8,%9}, {%0,%1,%2,%3};"
        : "+f"(c[0]), "+f"(c[1]), "+f"(c[2]), "+f"(c[3])
        : "r"(a0), "r"(a1), "r"(a2), "r"(a3), "r"(b0), "r"(b1));
}

__device__ __forceinline__ uint32_t smem_u32(const void* p) {
    uint32_t a;
    asm("{ .reg .u64 t; cvta.to.shared.u64 t, %1; cvt.u32.u64 %0, t; }" : "=r"(a) : "l"(p));
    return a;
}
__device__ __forceinline__ void cp16(uint32_t dst, const void* src, int sz) {
    asm volatile("cp.async.cg.shared.global [%0], [%1], 16, %2;"
                 :: "r"(dst), "l"(src), "r"(sz) : "memory");
}
#define CP_COMMIT() asm volatile("cp.async.commit_group;" ::: "memory")
#define CP_WAIT0()  asm volatile("cp.async.wait_group 0;" ::: "memory")

// pack a 16-k group (4 float4s, k contiguous) into permuted fp16:
// [k0,k1,k8,k9, k2,k3,k10,k11, k4,k5,k12,k13, k6,k7,k14,k15]
__device__ __forceinline__ void pack_group(float4 v0, float4 v1, float4 v2, float4 v3,
                                           H8* dst) {
    H8 o0, o1;
    o0.a = __floats2half2_rn(v0.x, v0.y); o0.b = __floats2half2_rn(v2.x, v2.y);
    o0.c = __floats2half2_rn(v0.z, v0.w); o0.d = __floats2half2_rn(v2.z, v2.w);
    o1.a = __floats2half2_rn(v1.x, v1.y); o1.b = __floats2half2_rn(v3.x, v3.y);
    o1.c = __floats2half2_rn(v1.z, v1.w); o1.d = __floats2half2_rn(v3.z, v3.w);
    dst[0] = o0; dst[1] = o1;
}

// ---------------- kernel 0: weight pre-convert (fp16 + k-permute) ----------------
__global__ void __launch_bounds__(256) wconv_kernel(const float* __restrict__ mw,
                                                    const float* __restrict__ lw) {
    int flat = blockIdx.x * 256 + threadIdx.x;   // 8192 rows x 32 groups = 262144
    int g16 = flat & 31;
    int rowp = flat >> 5;                        // mat*4096 + row
    int mat = rowp >> 12;
    const float4* s4 = (const float4*)((mat ? lw : mw) + (size_t)(rowp & 4095) * OBS + g16 * 16);
    float4 v0 = s4[0], v1 = s4[1], v2 = s4[2], v3 = s4[3];
    pack_group(v0, v1, v2, v3, (H8*)(g_wt + (size_t)rowp * OBS + g16 * 16));
}

// ---------------- kernel 1: router + x pre-convert ----------------
__global__ void __launch_bounds__(128) router_kernel(const float* __restrict__ x,
                                                     const float* __restrict__ rw,
                                                     const float* __restrict__ rb) {
    const int warp = threadIdx.x >> 5;
    const int lane = threadIdx.x & 31;
    const int b = blockIdx.x * 4 + warp;

    // lane owns k-group lane (k = 16*lane .. 16*lane+15)
    const float4* x4 = (const float4*)x + (size_t)b * 128;
    float4 v[4];
#pragma unroll
    for (int i = 0; i < 4; i++) v[i] = x4[4 * lane + i];

    pack_group(v[0], v[1], v[2], v[3], (H8*)(g_xt + (size_t)b * OBS + lane * 16));

    // partial logits, 16 parallel accumulators per lane
    float s[16];
#pragma unroll
    for (int e = 0; e < NE; e++) {
        const float4* w4 = (const float4*)rw + e * 128 + 4 * lane;
        float a = 0.f;
#pragma unroll
        for (int i = 0; i < 4; i++) {
            float4 w = __ldg(w4 + i);
            a = fmaf(v[i].x, w.x, fmaf(v[i].y, w.y, fmaf(v[i].z, w.z, fmaf(v[i].w, w.w, a))));
        }
        s[e] = a;
    }

    // register-folding butterfly
#pragma unroll
    for (int round = 0; round < 4; round++) {
        const int bit = 16 >> round;
        const int nreg = 8 >> round;
        bool hi = (lane & bit) != 0;
#pragma unroll
        for (int e = 0; e < 8; e++) {
            if (e < nreg) {
                float send = hi ? s[e] : s[e + nreg];
                float recv = __shfl_xor_sync(0xffffffffu, send, bit);
                float keep = hi ? s[e + nreg] : s[e];
                s[e] = keep + recv;
            }
        }
    }
    float lsum = s[0] + __shfl_xor_sync(0xffffffffu, s[0], 1);
    const int my_e = (lane >> 1) & 15;
    float logit = lsum + __ldg(rb + my_e);

    float m = logit;
#pragma unroll
    for (int off = 16; off; off >>= 1) m = fmaxf(m, __shfl_xor_sync(0xffffffffu, m, off));
    float pexp = expf(logit - m);
    float pc = (lane & 1) ? 0.f : pexp;
#pragma unroll
    for (int off = 16; off; off >>= 1) pc += __shfl_xor_sync(0xffffffffu, pc, off);
    float prob_pair = pexp / pc;
    float prob = __shfl_sync(0xffffffffu, prob_pair, 2 * (lane & 15));

    float cur = (lane < NE) ? prob : -1.f;
#pragma unroll
    for (int slot = 0; slot < TOPK; slot++) {
        float mx = cur;
#pragma unroll
        for (int off = 16; off; off >>= 1) mx = fmaxf(mx, __shfl_xor_sync(0xffffffffu, mx, off));
        unsigned bal = __ballot_sync(0xffffffffu, cur == mx);
        int sel = __ffs(bal) - 1;
        if (lane == sel) {
            int pos = atomicAdd(&g_cnt[lane], 1);
            g_ridx[lane * BATCH + pos] = b * 4 + slot;
            g_w[lane * BATCH + pos]    = prob;
            cur = -1.f;
        }
    }
}

// ---------------- kernel 2: fp16 mma grouped GEMM, K-chunk 128 ----------------
#define ABYTES 32768u                  // 128 rows x 256 B
#define BBYTES 65536u                  // 256 rows x 256 B
#define DYN_SMEM (2 * (ABYTES + BBYTES))   // 196608

__global__ void __launch_bounds__(512, 1)
expert_mma_kernel(const float* __restrict__ mb, const float* __restrict__ lb) {
    const int e   = blockIdx.y;
    const int mat = blockIdx.z;
    const int n   = g_cnt[e];
    const int start = blockIdx.x * TILE_M;
    if (start >= n) return;
    const int mrows = min(TILE_M, n - start);

    __shared__ int   bs[TILE_M];
    __shared__ int   ss[TILE_M];
    __shared__ float ws[TILE_M];
    extern __shared__ char smraw[];
    const uint32_t sb = smem_u32(smraw);

    const int t = threadIdx.x;
    if (t < TILE_M) {
        if (t < mrows) {
            int entry = g_ridx[e * BATCH + start + t];
            bs[t] = entry >> 2; ss[t] = entry & 3;
            ws[t] = g_w[e * BATCH + start + t];
        } else { bs[t] = 0; ss[t] = 0; ws[t] = 0.f; }
    }
    __syncthreads();

    const char* xt = (const char*)g_xt;
    const char* wt = (const char*)(g_wt + (size_t)((mat * NE + e) * ACT) * OBS);

    const int lane = t & 31;
    const int g  = lane >> 2;
    const int tg = lane & 3;
    const int wid = t >> 5;
    const int wm = wid & 3;
    const int wn = wid >> 2;

    // one K-chunk = 128 k = 256 B/row
    auto issue = [&](int kc, int buf) {
        const uint32_t abase = sb + buf * ABYTES;
#pragma unroll
        for (int i = 0; i < 4; i++) {               // A: 2048 quads
            int idx = t + 512 * i;
            int r = idx >> 4, q = idx & 15;
            const char* src = xt + (size_t)bs[r] * 1024 + kc * 256 + q * 16;
            uint32_t d = abase + (uint32_t)(r * 16 + (q ^ ((r & 7) << 1))) * 16u;
            cp16(d, src, (r < mrows) ? 16 : 0);
        }
        const uint32_t bbase = sb + 2 * ABYTES + buf * BBYTES;
#pragma unroll
        for (int i = 0; i < 8; i++) {               // B: 4096 quads
            int idx = t + 512 * i;
            int r = idx >> 4, q = idx & 15;
            const char* src = wt + (size_t)r * 1024 + kc * 256 + q * 16;
            cp16(bbase + (uint32_t)(r * 16 + (q ^ ((r & 7) << 1))) * 16u, src, 16);
        }
    };

    float acc[2][8][4];
#pragma unroll
    for (int im = 0; im < 2; im++)
#pragma unroll
        for (int in = 0; in < 8; in++)
#pragma unroll
            for (int c = 0; c < 4; c++) acc[im][in][c] = 0.f;

    issue(0, 0);
    CP_COMMIT();

    const int sw   = g << 1;          // quad-XOR (row&7 == g for all frag rows)
    const int qsub = tg >> 1;         // quad sub-index
    const int bsel = (tg & 1) * 8;    // byte within quad

#pragma unroll 1
    for (int kc = 0; kc < NCHUNK; kc++) {
        const int buf = kc & 1;
        CP_WAIT0();
        __syncthreads();
        if (kc + 1 < NCHUNK) { issue(kc + 1, buf ^ 1); CP_COMMIT(); }

        const char* Ab = smraw + buf * ABYTES;
        const char* Bb = smraw + 2 * ABYTES + buf * BBYTES;

#pragma unroll
        for (int ks = 0; ks < 8; ks++) {
            const int qoff = ((ks * 2 + qsub) ^ sw) * 16 + bsel;
            uint2 U[2], V[2];
#pragma unroll
            for (int im = 0; im < 2; im++) {
                const char* ap = Ab + (wm * 32 + im * 16 + g) * 256 + qoff;
                U[im] = *(const uint2*)ap;           // a0, a2
                V[im] = *(const uint2*)(ap + 2048);  // a1, a3 (row+8)
            }
#pragma unroll
            for (int in = 0; in < 8; in++) {
                uint2 W = *(const uint2*)(Bb + (wn * 64 + in * 8 + g) * 256 + qoff);
                mma_f16(acc[0][in], U[0].x, V[0].x, U[0].y, V[0].y, W.x, W.y);
                mma_f16(acc[1][in], U[1].x, V[1].x, U[1].y, V[1].y, W.x, W.y);
            }
        }
        __syncthreads();
    }

    // epilogue: w * (acc + bias) -> slot-indexed scratch (deterministic)
    const float* bias = (mat ? lb : mb) + e * ACT;
    float2 bv[8];
#pragma unroll
    for (int in = 0; in < 8; in++) {
        int c = wn * 64 + in * 8 + 2 * tg;
        bv[in] = make_float2(__ldg(bias + c), __ldg(bias + c + 1));
    }
#pragma unroll
    for (int im = 0; im < 2; im++) {
#pragma unroll
        for (int half = 0; half < 2; half++) {
            int r = wm * 32 + im * 16 + half * 8 + g;
            if (r < mrows) {
                float w = ws[r];
                float* dst = g_scr + ((size_t)(mat * 4 + ss[r]) * BATCH + bs[r]) * ACT
                           + wn * 64 + 2 * tg;
#pragma unroll
                for (int in = 0; in < 8; in++) {
                    float2 o;
                    o.x = w * (acc[im][in][half * 2 + 0] + bv[in].x);
                    o.y = w * (acc[im][in][half * 2 + 1] + bv[in].y);
                    *(float2*)(dst + in * 8) = o;
                }
            }
        }
    }
}

// ---------------- kernel 3: combine slots, tanh squash ----------------
__global__ void finalize_kernel(float* __restrict__ out) {
    const size_t N4 = (size_t)BATCH * ACT / 4;
    size_t i = (size_t)blockIdx.x * blockDim.x + threadIdx.x;
    if (i >= N4) return;
    const float4* s4 = (const float4*)g_scr;
    float4* out4 = (float4*)out;

    float4 a0 = s4[0 * N4 + i], a1 = s4[1 * N4 + i], a2 = s4[2 * N4 + i], a3 = s4[3 * N4 + i];
    float4 mm;
    mm.x = a0.x + a1.x + a2.x + a3.x;
    mm.y = a0.y + a1.y + a2.y + a3.y;
    mm.z = a0.z + a1.z + a2.z + a3.z;
    mm.w = a0.w + a1.w + a2.w + a3.w;
    out4[i] = mm;

    float4 b0 = s4[4 * N4 + i], b1 = s4[5 * N4 + i], b2 = s4[6 * N4 + i], b3 = s4[7 * N4 + i];
    float4 ll;
    ll.x = -5.f + 3.5f * (tanhf(b0.x + b1.x + b2.x + b3.x) + 1.f);
    ll.y = -5.f + 3.5f * (tanhf(b0.y + b1.y + b2.y + b3.y) + 1.f);
    ll.z = -5.f + 3.5f * (tanhf(b0.z + b1.z + b2.z + b3.z) + 1.f);
    ll.w = -5.f + 3.5f * (tanhf(b0.w + b1.w + b2.w + b3.w) + 1.f);
    out4[N4 + i] = ll;
}

// ---------------- launch ----------------
extern "C" void kernel_launch(void* const* d_in, const int* in_sizes, int n_in,
                              void* d_out, int out_size) {
    const float* x  = (const float*)d_in[0];
    const float* rw = (const float*)d_in[1];
    const float* rb = (const float*)d_in[2];
    const float* mw = (const float*)d_in[3];
    const float* mb = (const float*)d_in[4];
    const float* lw = (const float*)d_in[5];
    const float* lb = (const float*)d_in[6];
    float* out = (float*)d_out;

    cudaFuncSetAttribute(expert_mma_kernel,
                         cudaFuncAttributeMaxDynamicSharedMemorySize, DYN_SMEM);

    void* cntp = nullptr;
    cudaGetSymbolAddress(&cntp, g_cnt);
    cudaMemsetAsync(cntp, 0, sizeof(int) * NE);

    wconv_kernel<<<1024, 256>>>(mw, lw);
    router_kernel<<<BATCH / 4, 128>>>(x, rw, rb);

    dim3 g2(MAX_CHUNKS, NE, 2);
    expert_mma_kernel<<<g2, 512, DYN_SMEM>>>(mb, lb);

    finalize_kernel<<<(BATCH * ACT / 4 + 255) / 256, 256>>>(out);
}

// round 7
// speedup vs baseline: 9.1719x; 1.1342x over previous
#include <cuda_runtime.h>
#include <cuda_fp16.h>
#include <math.h>
#include <cstdint>

#define BATCH 16384
#define OBS   512
#define ACT   256
#define NE    16
#define TOPK  4
#define TILE_M 128
#define NCHUNK 4                       // K chunks of 128
#define MAX_CHUNKS (BATCH / TILE_M)

// ---------------- static device scratch ----------------
__device__ int    g_cnt[NE];
__device__ int    g_ridx[NE * BATCH];
__device__ float  g_w[NE * BATCH];
__device__ __half g_scr[(size_t)2 * 4 * BATCH * ACT];     // fp16 scratch [mat][slot][BATCH][ACT]
__device__ __half g_xt[(size_t)BATCH * OBS];              // fp16, k-permuted x
__device__ __half g_wt[(size_t)2 * NE * ACT * OBS];       // fp16, k-permuted weights

struct alignas(16) H8 { __half2 a, b, c, d; };

// m16n8k16 fp16 mma, fp32 accumulate
__device__ __forceinline__ void mma_f16(float* c,
                                        uint32_t a0, uint32_t a1, uint32_t a2, uint32_t a3,
                                        uint32_t b0, uint32_t b1) {
    asm volatile(
        "mma.sync.aligned.m16n8k16.row.col.f32.f16.f16.f32 "
        "{%0,%1,%2,%3}, {%4,%5,%6,%7}, {%8,%9}, {%0,%1,%2,%3};"
        : "+f"(c[0]), "+f"(c[1]), "+f"(c[2]), "+f"(c[3])
        : "r"(a0), "r"(a1), "r"(a2), "r"(a3), "r"(b0), "r"(b1));
}

__device__ __forceinline__ uint32_t smem_u32(const void* p) {
    uint32_t a;
    asm("{ .reg .u64 t; cvta.to.shared.u64 t, %1; cvt.u32.u64 %0, t; }" : "=r"(a) : "l"(p));
    return a;
}
__device__ __forceinline__ void cp16(uint32_t dst, const void* src, int sz) {
    asm volatile("cp.async.cg.shared.global [%0], [%1], 16, %2;"
                 :: "r"(dst), "l"(src), "r"(sz) : "memory");
}
#define CP_COMMIT() asm volatile("cp.async.commit_group;" ::: "memory")
#define CP_WAIT0()  asm volatile("cp.async.wait_group 0;" ::: "memory")

// pack a 16-k group (4 float4s, k contiguous) into permuted fp16:
// [k0,k1,k8,k9, k2,k3,k10,k11, k4,k5,k12,k13, k6,k7,k14,k15]
__device__ __forceinline__ void pack_group(float4 v0, float4 v1, float4 v2, float4 v3,
                                           H8* dst) {
    H8 o0, o1;
    o0.a = __floats2half2_rn(v0.x, v0.y); o0.b = __floats2half2_rn(v2.x, v2.y);
    o0.c = __floats2half2_rn(v0.z, v0.w); o0.d = __floats2half2_rn(v2.z, v2.w);
    o1.a = __floats2half2_rn(v1.x, v1.y); o1.b = __floats2half2_rn(v3.x, v3.y);
    o1.c = __floats2half2_rn(v1.z, v1.w); o1.d = __floats2half2_rn(v3.z, v3.w);
    dst[0] = o0; dst[1] = o1;
}

// ---------------- kernel 1: fused prep (wconv blocks + router blocks) ----------------
// blocks [0, 2048): weight fp16 convert+permute. blocks [2048, 4096): router, 2 rows/warp.
__global__ void __launch_bounds__(128) prep_kernel(const float* __restrict__ x,
                                                   const float* __restrict__ rw,
                                                   const float* __restrict__ rb,
                                                   const float* __restrict__ mw,
                                                   const float* __restrict__ lw) {
    const int bx = blockIdx.x;
    if (bx < 2048) {
        // ---- weight convert: one 16-k group per thread ----
        int flat = bx * 128 + threadIdx.x;           // 262144 = 8192 rows x 32 groups
        int g16 = flat & 31;
        int rowp = flat >> 5;                        // mat*4096 + row
        int mat = rowp >> 12;
        const float4* s4 = (const float4*)((mat ? lw : mw) + (size_t)(rowp & 4095) * OBS + g16 * 16);
        float4 v0 = s4[0], v1 = s4[1], v2 = s4[2], v3 = s4[3];
        pack_group(v0, v1, v2, v3, (H8*)(g_wt + (size_t)rowp * OBS + g16 * 16));
        return;
    }

    // ---- router: 2 rows per warp ----
    const int warp = threadIdx.x >> 5;
    const int lane = threadIdx.x & 31;
    const int b0 = (bx - 2048) * 8 + warp * 2;

    const float4* xa4 = (const float4*)x + (size_t)b0 * 128;
    const float4* xb4 = xa4 + 128;
    float4 va[4], vb[4];
#pragma unroll
    for (int i = 0; i < 4; i++) { va[i] = xa4[4 * lane + i]; vb[i] = xb4[4 * lane + i]; }

    pack_group(va[0], va[1], va[2], va[3], (H8*)(g_xt + (size_t)b0 * OBS + lane * 16));
    pack_group(vb[0], vb[1], vb[2], vb[3], (H8*)(g_xt + (size_t)(b0 + 1) * OBS + lane * 16));

    float s0[16], s1[16];
#pragma unroll
    for (int e = 0; e < NE; e++) {
        const float4* w4 = (const float4*)rw + e * 128 + 4 * lane;
        float a0 = 0.f, a1 = 0.f;
#pragma unroll
        for (int i = 0; i < 4; i++) {
            float4 w = __ldg(w4 + i);
            a0 = fmaf(va[i].x, w.x, fmaf(va[i].y, w.y, fmaf(va[i].z, w.z, fmaf(va[i].w, w.w, a0))));
            a1 = fmaf(vb[i].x, w.x, fmaf(vb[i].y, w.y, fmaf(vb[i].z, w.z, fmaf(vb[i].w, w.w, a1))));
        }
        s0[e] = a0; s1[e] = a1;
    }

    // register-folding butterfly for both rows
#pragma unroll
    for (int round = 0; round < 4; round++) {
        const int bit = 16 >> round;
        const int nreg = 8 >> round;
        bool hi = (lane & bit) != 0;
#pragma unroll
        for (int e = 0; e < 8; e++) {
            if (e < nreg) {
                float send0 = hi ? s0[e] : s0[e + nreg];
                float recv0 = __shfl_xor_sync(0xffffffffu, send0, bit);
                s0[e] = (hi ? s0[e + nreg] : s0[e]) + recv0;
                float send1 = hi ? s1[e] : s1[e + nreg];
                float recv1 = __shfl_xor_sync(0xffffffffu, send1, bit);
                s1[e] = (hi ? s1[e + nreg] : s1[e]) + recv1;
            }
        }
    }
    const int my_e = (lane >> 1) & 15;
    float rbias = __ldg(rb + my_e);
    float logit0 = s0[0] + __shfl_xor_sync(0xffffffffu, s0[0], 1) + rbias;
    float logit1 = s1[0] + __shfl_xor_sync(0xffffffffu, s1[0], 1) + rbias;

#pragma unroll
    for (int r = 0; r < 2; r++) {
        const int b = b0 + r;
        float logit = r ? logit1 : logit0;
        float m = logit;
#pragma unroll
        for (int off = 16; off; off >>= 1) m = fmaxf(m, __shfl_xor_sync(0xffffffffu, m, off));
        float pexp = expf(logit - m);
        float pc = (lane & 1) ? 0.f : pexp;
#pragma unroll
        for (int off = 16; off; off >>= 1) pc += __shfl_xor_sync(0xffffffffu, pc, off);
        float prob_pair = pexp / pc;
        float prob = __shfl_sync(0xffffffffu, prob_pair, 2 * (lane & 15));

        float cur = (lane < NE) ? prob : -1.f;
#pragma unroll
        for (int slot = 0; slot < TOPK; slot++) {
            float mx = cur;
#pragma unroll
            for (int off = 16; off; off >>= 1) mx = fmaxf(mx, __shfl_xor_sync(0xffffffffu, mx, off));
            unsigned bal = __ballot_sync(0xffffffffu, cur == mx);
            int sel = __ffs(bal) - 1;
            if (lane == sel) {
                int pos = atomicAdd(&g_cnt[lane], 1);
                g_ridx[lane * BATCH + pos] = b * 4 + slot;
                g_w[lane * BATCH + pos]    = prob;
                cur = -1.f;
            }
        }
    }
}

// ---------------- kernel 2: fp16 mma grouped GEMM, K-chunk 128 ----------------
#define ABYTES 32768u                  // 128 rows x 256 B
#define BBYTES 65536u                  // 256 rows x 256 B
#define DYN_SMEM (2 * (ABYTES + BBYTES))   // 196608

__global__ void __launch_bounds__(512, 1)
expert_mma_kernel(const float* __restrict__ mb, const float* __restrict__ lb) {
    const int e   = blockIdx.y;
    const int mat = blockIdx.z;
    const int n   = g_cnt[e];
    const int start = blockIdx.x * TILE_M;
    if (start >= n) return;
    const int mrows = min(TILE_M, n - start);

    __shared__ int   bs[TILE_M];
    __shared__ int   ss[TILE_M];
    __shared__ float ws[TILE_M];
    extern __shared__ char smraw[];
    const uint32_t sb = smem_u32(smraw);

    const int t = threadIdx.x;
    if (t < TILE_M) {
        if (t < mrows) {
            int entry = g_ridx[e * BATCH + start + t];
            bs[t] = entry >> 2; ss[t] = entry & 3;
            ws[t] = g_w[e * BATCH + start + t];
        } else { bs[t] = 0; ss[t] = 0; ws[t] = 0.f; }
    }
    __syncthreads();

    const char* xt = (const char*)g_xt;
    const char* wt = (const char*)(g_wt + (size_t)((mat * NE + e) * ACT) * OBS);

    const int lane = t & 31;
    const int g  = lane >> 2;
    const int tg = lane & 3;
    const int wid = t >> 5;
    const int wm = wid & 3;
    const int wn = wid >> 2;

    // one K-chunk = 128 k = 256 B/row
    auto issue = [&](int kc, int buf) {
        const uint32_t abase = sb + buf * ABYTES;
#pragma unroll
        for (int i = 0; i < 4; i++) {               // A: 2048 quads
            int idx = t + 512 * i;
            int r = idx >> 4, q = idx & 15;
            const char* src = xt + (size_t)bs[r] * 1024 + kc * 256 + q * 16;
            uint32_t d = abase + (uint32_t)(r * 16 + (q ^ ((r & 7) << 1))) * 16u;
            cp16(d, src, (r < mrows) ? 16 : 0);
        }
        const uint32_t bbase = sb + 2 * ABYTES + buf * BBYTES;
#pragma unroll
        for (int i = 0; i < 8; i++) {               // B: 4096 quads
            int idx = t + 512 * i;
            int r = idx >> 4, q = idx & 15;
            const char* src = wt + (size_t)r * 1024 + kc * 256 + q * 16;
            cp16(bbase + (uint32_t)(r * 16 + (q ^ ((r & 7) << 1))) * 16u, src, 16);
        }
    };

    float acc[2][8][4];
#pragma unroll
    for (int im = 0; im < 2; im++)
#pragma unroll
        for (int in = 0; in < 8; in++)
#pragma unroll
            for (int c = 0; c < 4; c++) acc[im][in][c] = 0.f;

    issue(0, 0);
    CP_COMMIT();

    const int sw   = g << 1;
    const int qsub = tg >> 1;
    const int bsel = (tg & 1) * 8;

#pragma unroll 1
    for (int kc = 0; kc < NCHUNK; kc++) {
        const int buf = kc & 1;
        CP_WAIT0();
        __syncthreads();
        if (kc + 1 < NCHUNK) { issue(kc + 1, buf ^ 1); CP_COMMIT(); }

        const char* Ab = smraw + buf * ABYTES;
        const char* Bb = smraw + 2 * ABYTES + buf * BBYTES;

#pragma unroll
        for (int ks = 0; ks < 8; ks++) {
            const int qoff = ((ks * 2 + qsub) ^ sw) * 16 + bsel;
            uint2 U[2], V[2];
#pragma unroll
            for (int im = 0; im < 2; im++) {
                const char* ap = Ab + (wm * 32 + im * 16 + g) * 256 + qoff;
                U[im] = *(const uint2*)ap;
                V[im] = *(const uint2*)(ap + 2048);
            }
#pragma unroll
            for (int in = 0; in < 8; in++) {
                uint2 W = *(const uint2*)(Bb + (wn * 64 + in * 8 + g) * 256 + qoff);
                mma_f16(acc[0][in], U[0].x, V[0].x, U[0].y, V[0].y, W.x, W.y);
                mma_f16(acc[1][in], U[1].x, V[1].x, U[1].y, V[1].y, W.x, W.y);
            }
        }
        __syncthreads();
    }

    // epilogue: w * (acc + bias) -> fp16 slot-indexed scratch (deterministic)
    const float* bias = (mat ? lb : mb) + e * ACT;
    float2 bv[8];
#pragma unroll
    for (int in = 0; in < 8; in++) {
        int c = wn * 64 + in * 8 + 2 * tg;
        bv[in] = make_float2(__ldg(bias + c), __ldg(bias + c + 1));
    }
#pragma unroll
    for (int im = 0; im < 2; im++) {
#pragma unroll
        for (int half = 0; half < 2; half++) {
            int r = wm * 32 + im * 16 + half * 8 + g;
            if (r < mrows) {
                float w = ws[r];
                __half* dst = g_scr + ((size_t)(mat * 4 + ss[r]) * BATCH + bs[r]) * ACT
                            + wn * 64 + 2 * tg;
#pragma unroll
                for (int in = 0; in < 8; in++) {
                    float ox = w * (acc[im][in][half * 2 + 0] + bv[in].x);
                    float oy = w * (acc[im][in][half * 2 + 1] + bv[in].y);
                    *(__half2*)(dst + in * 8) = __floats2half2_rn(ox, oy);
                }
            }
        }
    }
}

// ---------------- kernel 3: combine slots (fp16 scratch), tanh squash ----------------
__global__ void __launch_bounds__(256) finalize_kernel(float* __restrict__ out) {
    const size_t N8 = (size_t)BATCH * ACT / 8;   // uint4 (8 halves) per slot array
    const size_t N4 = (size_t)BATCH * ACT / 4;   // float4 per output matrix
    size_t i = (size_t)blockIdx.x * 256 + threadIdx.x;
    if (i >= N8) return;
    const uint4* s = (const uint4*)g_scr;
    float4* out4 = (float4*)out;

    float acc[8];
#pragma unroll
    for (int j = 0; j < 8; j++) acc[j] = 0.f;
#pragma unroll
    for (int sl = 0; sl < 4; sl++) {
        uint4 u = s[sl * N8 + i];
        float2 f0 = __half22float2(*(__half2*)&u.x);
        float2 f1 = __half22float2(*(__half2*)&u.y);
        float2 f2 = __half22float2(*(__half2*)&u.z);
        float2 f3 = __half22float2(*(__half2*)&u.w);
        acc[0] += f0.x; acc[1] += f0.y; acc[2] += f1.x; acc[3] += f1.y;
        acc[4] += f2.x; acc[5] += f2.y; acc[6] += f3.x; acc[7] += f3.y;
    }
    out4[2 * i]     = make_float4(acc[0], acc[1], acc[2], acc[3]);
    out4[2 * i + 1] = make_float4(acc[4], acc[5], acc[6], acc[7]);

#pragma unroll
    for (int j = 0; j < 8; j++) acc[j] = 0.f;
#pragma unroll
    for (int sl = 4; sl < 8; sl++) {
        uint4 u = s[sl * N8 + i];
        float2 f0 = __half22float2(*(__half2*)&u.x);
        float2 f1 = __half22float2(*(__half2*)&u.y);
        float2 f2 = __half22float2(*(__half2*)&u.z);
        float2 f3 = __half22float2(*(__half2*)&u.w);
        acc[0] += f0.x; acc[1] += f0.y; acc[2] += f1.x; acc[3] += f1.y;
        acc[4] += f2.x; acc[5] += f2.y; acc[6] += f3.x; acc[7] += f3.y;
    }
#pragma unroll
    for (int j = 0; j < 8; j++) acc[j] = -5.f + 3.5f * (tanhf(acc[j]) + 1.f);
    out4[N4 + 2 * i]     = make_float4(acc[0], acc[1], acc[2], acc[3]);
    out4[N4 + 2 * i + 1] = make_float4(acc[4], acc[5], acc[6], acc[7]);
}

// ---------------- launch ----------------
extern "C" void kernel_launch(void* const* d_in, const int* in_sizes, int n_in,
                              void* d_out, int out_size) {
    const float* x  = (const float*)d_in[0];
    const float* rw = (const float*)d_in[1];
    const float* rb = (const float*)d_in[2];
    const float* mw = (const float*)d_in[3];
    const float* mb = (const float*)d_in[4];
    const float* lw = (const float*)d_in[5];
    const float* lb = (const float*)d_in[6];
    float* out = (float*)d_out;

    cudaFuncSetAttribute(expert_mma_kernel,
                         cudaFuncAttributeMaxDynamicSharedMemorySize, DYN_SMEM);

    void* cntp = nullptr;
    cudaGetSymbolAddress(&cntp, g_cnt);
    cudaMemsetAsync(cntp, 0, sizeof(int) * NE);

    prep_kernel<<<4096, 128>>>(x, rw, rb, mw, lw);

    dim3 g2(MAX_CHUNKS, NE, 2);
    expert_mma_kernel<<<g2, 512, DYN_SMEM>>>(mb, lb);

    finalize_kernel<<<(BATCH * ACT / 8 + 255) / 256, 256>>>(out);
}